// round 14
// baseline (speedup 1.0000x reference)
#include <cuda_runtime.h>

#define N 1024
#define D 64
#define H 8
#define IDXE 64
#define NSPLIT 16     // spmm m-splits (4 chunks of KC per block)
#define NCHUNK 4
#define KC 16         // m-chunk staged at a time
#define NT 128        // n-tile for spmm
#define TG_SPLIT 8
#define PADA 132
#define PADU 68
#define PADW 68
#define PADX 66

typedef unsigned long long ull;

// ---------------- f32x2 helpers ----------------
__device__ __forceinline__ ull pk2(float lo, float hi) {
    ull r; asm("mov.b64 %0, {%1,%2};" : "=l"(r) : "f"(lo), "f"(hi)); return r;
}
__device__ __forceinline__ ull dup2(float x) {
    ull r; asm("mov.b64 %0, {%1,%1};" : "=l"(r) : "f"(x)); return r;
}
__device__ __forceinline__ ull fma2(ull a, ull b, ull c) {
    ull d; asm("fma.rn.f32x2 %0, %1, %2, %3;" : "=l"(d) : "l"(a), "l"(b), "l"(c)); return d;
}
__device__ __forceinline__ ull add2(ull a, ull b) {
    ull d; asm("add.rn.f32x2 %0, %1, %2;" : "=l"(d) : "l"(a), "l"(b)); return d;
}
__device__ __forceinline__ ull mul2(ull a, ull b) {
    ull d; asm("mul.rn.f32x2 %0, %1, %2;" : "=l"(d) : "l"(a), "l"(b)); return d;
}
__device__ __forceinline__ ull relu2(ull v) {
    float lo, hi;
    asm("mov.b64 {%0,%1}, %2;" : "=f"(lo), "=f"(hi) : "l"(v));
    lo = fmaxf(lo, 0.f); hi = fmaxf(hi, 0.f);
    return pk2(lo, hi);
}
__device__ __forceinline__ void unpk2(ull v, float& lo, float& hi) {
    asm("mov.b64 {%0,%1}, %2;" : "=f"(lo), "=f"(hi) : "l"(v));
}

// ---------------- static scratch ----------------
__device__ float g_a[N * N];
__device__ float g_ad[N * N];
__device__ float g_rowpb[2][N][H];
__device__ float g_colT[2][H][N];
__device__ float g_tgp[TG_SPLIT][N];
__device__ float g_xbuf[2][N * D];
__device__ float g_u[5][N * D];
__device__ float g_part[NSPLIT][N * D];

// ---------------- projections ----------------
__global__ void proj_kernel(const float* __restrict__ idx_emb,
                            const float* __restrict__ W1,
                            const float* __restrict__ b1) {
    int id = blockIdx.x * blockDim.x + threadIdx.x;   // 32768 threads
    int h  = id & 7;
    int s  = (id >> 3) & 1;
    int rc = (id >> 4) & 1;
    int n  = id >> 5;
    const float* w = W1 + s * (H * 129) + h * 129 + 1 + rc * IDXE;
    const float* e = idx_emb + n * IDXE;
    float acc = 0.f;
#pragma unroll 16
    for (int k = 0; k < IDXE; k++) acc = fmaf(e[k], w[k], acc);
    if (rc == 0) g_rowpb[s][n][h] = acc + b1[s * H + h];
    else         g_colT[s][h][n]  = acc;
}

// ---------------- tg partials ----------------
__global__ void tg_kernel(const float* __restrict__ t_grad) {
    int n = blockIdx.x * 256 + threadIdx.x;
    int s = blockIdx.y;
    const int R = N / TG_SPLIT;
    float acc = 0.f;
    for (int m = s * R; m < (s + 1) * R; m++) acc += t_grad[m * N + n];
    g_tgp[s][n] = acc;
}

// ---------------- edge MLP: 2 packs (4 edges), vectorized shared loads ----------------
__device__ __forceinline__ void mlp2x2(ull a0, ull a1,
                                       const ull* __restrict__ wa,
                                       const ull* __restrict__ rc0,
                                       const ull* __restrict__ rc1,
                                       const ull* __restrict__ W2,
                                       const ull* __restrict__ b2,
                                       const ull* __restrict__ W3, ull b3v,
                                       ull& o0, ull& o1) {
    ull h1a[H], h1b[H];
#pragma unroll
    for (int h = 0; h < H; h += 2) {
        ulonglong2 w = *(const ulonglong2*)(wa + h);
        h1a[h]     = relu2(fma2(a0, w.x, rc0[h]));
        h1b[h]     = relu2(fma2(a1, w.x, rc1[h]));
        h1a[h + 1] = relu2(fma2(a0, w.y, rc0[h + 1]));
        h1b[h + 1] = relu2(fma2(a1, w.y, rc1[h + 1]));
    }
    o0 = b3v; o1 = b3v;
#pragma unroll
    for (int k = 0; k < H; k += 2) {
        ulonglong2 bb = *(const ulonglong2*)(b2 + k);
        ull t0 = bb.x, t1 = bb.x, t2 = bb.y, t3 = bb.y;
#pragma unroll
        for (int h = 0; h < H; h += 2) {
            ulonglong2 wk0 = *(const ulonglong2*)(W2 + k * H + h);
            ulonglong2 wk1 = *(const ulonglong2*)(W2 + (k + 1) * H + h);
            t0 = fma2(wk0.x, h1a[h], t0);     t1 = fma2(wk0.x, h1b[h], t1);
            t0 = fma2(wk0.y, h1a[h + 1], t0); t1 = fma2(wk0.y, h1b[h + 1], t1);
            t2 = fma2(wk1.x, h1a[h], t2);     t3 = fma2(wk1.x, h1b[h], t3);
            t2 = fma2(wk1.y, h1a[h + 1], t2); t3 = fma2(wk1.y, h1b[h + 1], t3);
        }
        ulonglong2 w3 = *(const ulonglong2*)(W3 + k);
        o0 = fma2(w3.x, relu2(t0), o0);
        o1 = fma2(w3.x, relu2(t1), o1);
        o0 = fma2(w3.y, relu2(t2), o0);
        o1 = fma2(w3.y, relu2(t3), o1);
    }
}

__global__ void __launch_bounds__(256, 4) msg_kernel(const float* __restrict__ adj,
                           const float* __restrict__ adjd,
                           const float* __restrict__ W1,
                           const float* __restrict__ W2,
                           const float* __restrict__ b2,
                           const float* __restrict__ W3,
                           const float* __restrict__ b3) {
    __shared__ __align__(16) ull wa2[2][H], W2d[2][H * H], b2d[2][H], W3d[2][H], b3d[2];
    __shared__ float rcn[2][8][H];
    __shared__ __align__(16) ull ccm2[2][H][64];     // 128 m per block = 64 packs
    int tid = threadIdx.x;
    int mb = blockIdx.x * 128, nb = blockIdx.y * 8;

    if (tid < 16) {
        int s = tid >> 3, h = tid & 7;
        wa2[s][h] = dup2(W1[s * (H * 129) + h * 129]);
        b2d[s][h] = dup2(b2[tid]);
        W3d[s][h] = dup2(W3[tid]);
    }
    if (tid < 2) b3d[tid] = dup2(b3[tid]);
    if (tid >= 32 && tid < 160) {
        int i = tid - 32;
        W2d[i >> 6][i & 63] = dup2(W2[i]);
    }
    if (tid < 128) {
        int s = tid >> 6, r = (tid >> 3) & 7, h = tid & 7;
        rcn[s][r][h] = g_rowpb[s][nb + r][h];
    }
    for (int i = tid; i < 1024; i += 256) {
        int s = i >> 9, h = (i >> 6) & 7, mp = i & 63;
        float2 c = *(const float2*)(&g_colT[s][h][mb + 2 * mp]);
        ccm2[s][h][mp] = pk2(c.x, c.y);
    }
    __syncthreads();

    int mg = tid & 31, nloc = tid >> 5;
    int m0 = mb + 4 * mg, n = nb + nloc;
    float4 av  = *(const float4*)(adj  + n * N + m0);
    float4 adv = *(const float4*)(adjd + n * N + m0);

    {
        ull rc0[H], rc1[H];
#pragma unroll
        for (int h = 0; h < H; h++) {
            ull rn = dup2(rcn[0][nloc][h]);
            ulonglong2 c = *(const ulonglong2*)(&ccm2[0][h][2 * mg]);
            rc0[h] = add2(rn, c.x);
            rc1[h] = add2(rn, c.y);
        }
        ull o0, o1;
        mlp2x2(pk2(av.x, av.y), pk2(av.z, av.w), wa2[0], rc0, rc1,
               W2d[0], b2d[0], W3d[0], b3d[0], o0, o1);
        ulonglong2 v; v.x = o0; v.y = o1;
        *(ulonglong2*)(g_a + n * N + m0) = v;
    }
    {
        ull rc0[H], rc1[H];
#pragma unroll
        for (int h = 0; h < H; h++) {
            ull rn = dup2(rcn[1][nloc][h]);
            ulonglong2 c = *(const ulonglong2*)(&ccm2[1][h][2 * mg]);
            rc0[h] = add2(rn, c.x);
            rc1[h] = add2(rn, c.y);
        }
        ull o0, o1;
        mlp2x2(pk2(adv.x, adv.y), pk2(adv.z, adv.w), wa2[1], rc0, rc1,
               W2d[1], b2d[1], W3d[1], b3d[1], o0, o1);
        ulonglong2 v; v.x = o0; v.y = o1;
        *(ulonglong2*)(g_ad + n * N + m0) = v;
    }
}

// ---------------- xu_first: u_q[layer0] = y @ W[0][q], q=0..4 ----------------
__global__ void __launch_bounds__(256) xu_first_kernel(const float* __restrict__ y,
                                                       const float* __restrict__ gnn_W) {
    extern __shared__ float sm[];
    float* Ws = sm;                  // 5 x [64][PADW]
    float* xs = Ws + 5 * 64 * PADW;  // [8][PADX]
    int tid = threadIdx.x;
    int m0 = blockIdx.x * 8;
    const float* Wbase = gnn_W;      // layer 0

    for (int i = tid; i < 5 * 4096; i += 256) {
        int q = i >> 12, k = (i >> 6) & 63, c = i & 63;
        Ws[q * 64 * PADW + k * PADW + c] = Wbase[i];
    }
    for (int i = tid; i < 8 * D; i += 256) {
        int r = i >> 6, k = i & 63;
        xs[r * PADX + k] = y[(m0 + r) * D + k];
    }
    __syncthreads();

    int r  = tid >> 5;              // 0..7
    int c2 = (tid & 31) * 2;        // 0..62
#pragma unroll
    for (int q = 0; q < 5; q++) {
        const float* Wq = Ws + q * 64 * PADW + c2;
        const float* xr = xs + r * PADX;
        ull acc = 0ull;
#pragma unroll 16
        for (int k = 0; k < 64; k++)
            acc = fma2(dup2(xr[k]), *(const ull*)(Wq + k * PADW), acc);
        *(ull*)(g_u[q] + (m0 + r) * D + c2) = acc;
    }
}

// ---------------- xu: x_l = relu(partials + u4 + b[l]); u_q = x_l @ W[l+1][q] ----------------
__global__ void __launch_bounds__(256) xu_kernel(const float* __restrict__ gnn_W,
                                                 const float* __restrict__ gnn_b,
                                                 int layer) {
    extern __shared__ float sm[];
    float* Ws = sm;                  // 5 x [64][PADW]  (weights of layer+1)
    float* xs = Ws + 5 * 64 * PADW;  // [8][PADX]
    int tid = threadIdx.x;
    int m0 = blockIdx.x * 8;
    const float* Wbase = gnn_W + (layer + 1) * 5 * 4096;

    for (int i = tid; i < 5 * 4096; i += 256) {
        int q = i >> 12, k = (i >> 6) & 63, c = i & 63;
        Ws[q * 64 * PADW + k * PADW + c] = Wbase[i];
    }

    // phase A: reduce partials -> x_l (one f32x2 pair per thread)
    int r  = tid >> 5;              // 0..7
    int c2 = (tid & 31) * 2;        // 0..62
    int off = (m0 + r) * D + c2;
    ull acc = add2(*(const ull*)(g_u[4] + off),
                   pk2(gnn_b[layer * D + c2], gnn_b[layer * D + c2 + 1]));
#pragma unroll
    for (int s = 0; s < NSPLIT; s++)
        acc = add2(acc, *(const ull*)(g_part[s] + off));
    acc = relu2(acc);
    *(ull*)(g_xbuf[layer] + off) = acc;
    *(ull*)(xs + r * PADX + c2) = acc;
    __syncthreads();

    // phase B: u_q for next layer
#pragma unroll
    for (int q = 0; q < 5; q++) {
        const float* Wq = Ws + q * 64 * PADW + c2;
        const float* xr = xs + r * PADX;
        ull a = 0ull;
#pragma unroll 16
        for (int k = 0; k < 64; k++)
            a = fma2(dup2(xr[k]), *(const ull*)(Wq + k * PADW), a);
        *(ull*)(g_u[q] + (m0 + r) * D + c2) = a;
    }
}

// ---------------- fused 4-way product: NT=128, 4 chunks of KC=16, 3 CTA/SM ----------------
__global__ void __launch_bounds__(256, 3) spmm_kernel() {
    extern __shared__ float sm[];
    float* a_ds = sm;                    // [KC][PADA]
    float* a_ts = a_ds + KC * PADA;
    float* d_ds = a_ts + KC * PADA;
    float* d_ts = d_ds + KC * PADA;
    float* u0s  = d_ts + KC * PADA;      // [KC][PADU]
    float* u1s  = u0s + KC * PADU;
    float* u2s  = u1s + KC * PADU;
    float* u3s  = u2s + KC * PADU;

    int tid = threadIdx.x;
    int n0 = blockIdx.x * NT;
    int mbase = blockIdx.y * (NCHUNK * KC);

    int tr = tid >> 4;      // 0..15 -> rows i0 = tr*8
    int tc = tid & 15;      // 0..15 -> cols c0 = tc*4
    int i0 = tr * 8, c0 = tc * 4;

    ull acc[8][2];
#pragma unroll
    for (int i = 0; i < 8; i++) { acc[i][0] = 0ull; acc[i][1] = 0ull; }

#pragma unroll
    for (int chunk = 0; chunk < NCHUNK; chunk++) {
        int m0 = mbase + chunk * KC;
        if (chunk > 0) __syncthreads();    // ensure prior reads done before restage

        // stage direct tiles: read a[(n0+i), m0+j], store [j][i]
        for (int idx = tid; idx < NT * KC; idx += 256) {
            int i = idx >> 4, j = idx & 15;
            a_ds[j * PADA + i] = g_a[(n0 + i) * N + m0 + j];
            d_ds[j * PADA + i] = g_ad[(n0 + i) * N + m0 + j];
        }
        // stage transposed tiles: read a[(m0+j), n0+i] coalesced
        for (int idx = tid; idx < NT * KC; idx += 256) {
            int j = idx >> 7, i = idx & 127;
            a_ts[j * PADA + i] = g_a[(m0 + j) * N + n0 + i];
            d_ts[j * PADA + i] = g_ad[(m0 + j) * N + n0 + i];
        }
        for (int idx = tid; idx < KC * D; idx += 256) {
            int j = idx >> 6, d = idx & 63;
            u0s[j * PADU + d] = g_u[0][(m0 + j) * D + d];
            u1s[j * PADU + d] = g_u[1][(m0 + j) * D + d];
            u2s[j * PADU + d] = g_u[2][(m0 + j) * D + d];
            u3s[j * PADU + d] = g_u[3][(m0 + j) * D + d];
        }
        __syncthreads();

#pragma unroll 2
        for (int j = 0; j < KC; j++) {
            ulonglong2 u0p = *(const ulonglong2*)(u0s + j * PADU + c0);
            ulonglong2 u1p = *(const ulonglong2*)(u1s + j * PADU + c0);
            ulonglong2 u2p = *(const ulonglong2*)(u2s + j * PADU + c0);
            ulonglong2 u3p = *(const ulonglong2*)(u3s + j * PADU + c0);
            float aD[8], aT[8], bD[8], bT[8];
            *(float4*)(aD)     = *(const float4*)(a_ds + j * PADA + i0);
            *(float4*)(aD + 4) = *(const float4*)(a_ds + j * PADA + i0 + 4);
            *(float4*)(aT)     = *(const float4*)(a_ts + j * PADA + i0);
            *(float4*)(aT + 4) = *(const float4*)(a_ts + j * PADA + i0 + 4);
            *(float4*)(bD)     = *(const float4*)(d_ds + j * PADA + i0);
            *(float4*)(bD + 4) = *(const float4*)(d_ds + j * PADA + i0 + 4);
            *(float4*)(bT)     = *(const float4*)(d_ts + j * PADA + i0);
            *(float4*)(bT + 4) = *(const float4*)(d_ts + j * PADA + i0 + 4);
#pragma unroll
            for (int i = 0; i < 8; i++) {
                ull aDd = dup2(aD[i]), aTd = dup2(aT[i]);
                ull bDd = dup2(bD[i]), bTd = dup2(bT[i]);
                acc[i][0] = fma2(aDd, u0p.x, fma2(aTd, u1p.x, fma2(bDd, u2p.x, fma2(bTd, u3p.x, acc[i][0]))));
                acc[i][1] = fma2(aDd, u0p.y, fma2(aTd, u1p.y, fma2(bDd, u2p.y, fma2(bTd, u3p.y, acc[i][1]))));
            }
        }
    }

    float* outp = g_part[blockIdx.y];
#pragma unroll
    for (int i = 0; i < 8; i++) {
        ulonglong2 v; v.x = acc[i][0]; v.y = acc[i][1];
        *(ulonglong2*)(outp + (n0 + i0 + i) * D + c0) = v;
    }
}

// ---------------- final: partials + u4 + b[2], scale by tg ----------------
__global__ void __launch_bounds__(256) final_kernel(float* __restrict__ out,
                                                    const float* __restrict__ gnn_b) {
    int tid = threadIdx.x;
    int m0 = blockIdx.x * 8;            // grid 128
    int r  = tid >> 5;
    int c2 = (tid & 31) * 2;
    int off = (m0 + r) * D + c2;
    ull acc = add2(*(const ull*)(g_u[4] + off),
                   pk2(gnn_b[2 * D + c2], gnn_b[2 * D + c2 + 1]));
#pragma unroll
    for (int s = 0; s < NSPLIT; s++)
        acc = add2(acc, *(const ull*)(g_part[s] + off));
    float tg = 0.f;
#pragma unroll
    for (int s = 0; s < TG_SPLIT; s++) tg += g_tgp[s][m0 + r];
    tg *= (1.0f / N);
    acc = mul2(acc, dup2(tg));
    *(ull*)(out + off) = acc;
}

// ---------------- launch ----------------
extern "C" void kernel_launch(void* const* d_in, const int* in_sizes, int n_in,
                              void* d_out, int out_size) {
    const float* y       = (const float*)d_in[0];
    const float* adj     = (const float*)d_in[1];
    const float* adjd    = (const float*)d_in[2];
    const float* t_grad  = (const float*)d_in[3];
    const float* idx_emb = (const float*)d_in[4];
    const float* msg_W1  = (const float*)d_in[5];
    const float* msg_b1  = (const float*)d_in[6];
    const float* msg_W2  = (const float*)d_in[7];
    const float* msg_b2  = (const float*)d_in[8];
    const float* msg_W3  = (const float*)d_in[9];
    const float* msg_b3  = (const float*)d_in[10];
    const float* gnn_W   = (const float*)d_in[11];
    const float* gnn_b   = (const float*)d_in[12];
    float* out = (float*)d_out;

    const int spmm_smem = (4 * KC * PADA + 4 * KC * PADU) * (int)sizeof(float); // 51,200
    const int xu_smem   = (5 * 64 * PADW + 8 * PADX) * (int)sizeof(float);      // 89,152
    cudaFuncSetAttribute(spmm_kernel, cudaFuncAttributeMaxDynamicSharedMemorySize, spmm_smem);
    cudaFuncSetAttribute(xu_kernel, cudaFuncAttributeMaxDynamicSharedMemorySize, xu_smem);
    cudaFuncSetAttribute(xu_first_kernel, cudaFuncAttributeMaxDynamicSharedMemorySize, xu_smem);

    cudaStream_t s2, s3;
    cudaEvent_t eF, eJ, eU;
    cudaStreamCreateWithFlags(&s2, cudaStreamNonBlocking);
    cudaStreamCreateWithFlags(&s3, cudaStreamNonBlocking);
    cudaEventCreateWithFlags(&eF, cudaEventDisableTiming);
    cudaEventCreateWithFlags(&eJ, cudaEventDisableTiming);
    cudaEventCreateWithFlags(&eU, cudaEventDisableTiming);

    cudaEventRecord(eF, 0);
    cudaStreamWaitEvent(s2, eF, 0);
    cudaStreamWaitEvent(s3, eF, 0);

    // side stream B: tg partials
    tg_kernel<<<dim3(4, TG_SPLIT), 256, 0, s2>>>(t_grad);
    cudaEventRecord(eJ, s2);

    // side stream C: layer-0 u projections (independent of adj path)
    xu_first_kernel<<<128, 256, xu_smem, s3>>>(y, gnn_W);
    cudaEventRecord(eU, s3);

    // main: proj -> msg
    proj_kernel<<<128, 256>>>(idx_emb, msg_W1, msg_b1);
    msg_kernel<<<dim3(8, 128), 256>>>(adj, adjd, msg_W1, msg_W2, msg_b2, msg_W3, msg_b3);

    cudaStreamWaitEvent(0, eU, 0);
    for (int l = 0; l < 3; l++) {
        spmm_kernel<<<dim3(N / NT, NSPLIT), 256, spmm_smem>>>();
        if (l < 2) {
            xu_kernel<<<128, 256, xu_smem>>>(gnn_W, gnn_b, l);
        } else {
            cudaStreamWaitEvent(0, eJ, 0);
            final_kernel<<<128, 256>>>(out, gnn_b);
        }
    }

    // release per-call stream/event resources (side streams already joined)
    cudaEventDestroy(eF);
    cudaEventDestroy(eJ);
    cudaEventDestroy(eU);
    cudaStreamDestroy(s2);
    cudaStreamDestroy(s3);
}

// round 16
// speedup vs baseline: 1.0769x; 1.0769x over previous
#include <cuda_runtime.h>

#define N 1024
#define D 64
#define H 8
#define IDXE 64
#define NSPLIT 32     // spmm m-splits (2 chunks of KC per block)
#define NCHUNK 2
#define KC 16         // m-chunk staged at a time
#define NT 128        // n-tile for spmm
#define TG_SPLIT 8
#define PADA 132
#define PADU 68
#define PADW 68
#define PADX 66

typedef unsigned long long ull;

// ---------------- f32x2 helpers ----------------
__device__ __forceinline__ ull pk2(float lo, float hi) {
    ull r; asm("mov.b64 %0, {%1,%2};" : "=l"(r) : "f"(lo), "f"(hi)); return r;
}
__device__ __forceinline__ ull dup2(float x) {
    ull r; asm("mov.b64 %0, {%1,%1};" : "=l"(r) : "f"(x)); return r;
}
__device__ __forceinline__ ull fma2(ull a, ull b, ull c) {
    ull d; asm("fma.rn.f32x2 %0, %1, %2, %3;" : "=l"(d) : "l"(a), "l"(b), "l"(c)); return d;
}
__device__ __forceinline__ ull add2(ull a, ull b) {
    ull d; asm("add.rn.f32x2 %0, %1, %2;" : "=l"(d) : "l"(a), "l"(b)); return d;
}
__device__ __forceinline__ ull mul2(ull a, ull b) {
    ull d; asm("mul.rn.f32x2 %0, %1, %2;" : "=l"(d) : "l"(a), "l"(b)); return d;
}
__device__ __forceinline__ ull relu2(ull v) {
    float lo, hi;
    asm("mov.b64 {%0,%1}, %2;" : "=f"(lo), "=f"(hi) : "l"(v));
    lo = fmaxf(lo, 0.f); hi = fmaxf(hi, 0.f);
    return pk2(lo, hi);
}
__device__ __forceinline__ void unpk2(ull v, float& lo, float& hi) {
    asm("mov.b64 {%0,%1}, %2;" : "=f"(lo), "=f"(hi) : "l"(v));
}

// ---------------- static scratch ----------------
__device__ float g_a[N * N];
__device__ float g_ad[N * N];
__device__ float g_rowpb[2][N][H];
__device__ float g_colT[2][H][N];
__device__ float g_tgp[TG_SPLIT][N];
__device__ float g_xbuf[2][N * D];
__device__ float g_u[5][N * D];
__device__ float g_part[NSPLIT][N * D];

// ---------------- projections ----------------
__global__ void proj_kernel(const float* __restrict__ idx_emb,
                            const float* __restrict__ W1,
                            const float* __restrict__ b1) {
    int id = blockIdx.x * blockDim.x + threadIdx.x;   // 32768 threads
    int h  = id & 7;
    int s  = (id >> 3) & 1;
    int rc = (id >> 4) & 1;
    int n  = id >> 5;
    const float* w = W1 + s * (H * 129) + h * 129 + 1 + rc * IDXE;
    const float* e = idx_emb + n * IDXE;
    float acc = 0.f;
#pragma unroll 16
    for (int k = 0; k < IDXE; k++) acc = fmaf(e[k], w[k], acc);
    if (rc == 0) g_rowpb[s][n][h] = acc + b1[s * H + h];
    else         g_colT[s][h][n]  = acc;
}

// ---------------- tg partials ----------------
__global__ void tg_kernel(const float* __restrict__ t_grad) {
    int n = blockIdx.x * 256 + threadIdx.x;
    int s = blockIdx.y;
    const int R = N / TG_SPLIT;
    float acc = 0.f;
    for (int m = s * R; m < (s + 1) * R; m++) acc += t_grad[m * N + n];
    g_tgp[s][n] = acc;
}

// ---------------- edge MLP: 2 packs (4 edges), vectorized shared loads ----------------
__device__ __forceinline__ void mlp2x2(ull a0, ull a1,
                                       const ull* __restrict__ wa,
                                       const ull* __restrict__ rc0,
                                       const ull* __restrict__ rc1,
                                       const ull* __restrict__ W2,
                                       const ull* __restrict__ b2,
                                       const ull* __restrict__ W3, ull b3v,
                                       ull& o0, ull& o1) {
    ull h1a[H], h1b[H];
#pragma unroll
    for (int h = 0; h < H; h += 2) {
        ulonglong2 w = *(const ulonglong2*)(wa + h);
        h1a[h]     = relu2(fma2(a0, w.x, rc0[h]));
        h1b[h]     = relu2(fma2(a1, w.x, rc1[h]));
        h1a[h + 1] = relu2(fma2(a0, w.y, rc0[h + 1]));
        h1b[h + 1] = relu2(fma2(a1, w.y, rc1[h + 1]));
    }
    o0 = b3v; o1 = b3v;
#pragma unroll
    for (int k = 0; k < H; k += 2) {
        ulonglong2 bb = *(const ulonglong2*)(b2 + k);
        ull t0 = bb.x, t1 = bb.x, t2 = bb.y, t3 = bb.y;
#pragma unroll
        for (int h = 0; h < H; h += 2) {
            ulonglong2 wk0 = *(const ulonglong2*)(W2 + k * H + h);
            ulonglong2 wk1 = *(const ulonglong2*)(W2 + (k + 1) * H + h);
            t0 = fma2(wk0.x, h1a[h], t0);     t1 = fma2(wk0.x, h1b[h], t1);
            t0 = fma2(wk0.y, h1a[h + 1], t0); t1 = fma2(wk0.y, h1b[h + 1], t1);
            t2 = fma2(wk1.x, h1a[h], t2);     t3 = fma2(wk1.x, h1b[h], t3);
            t2 = fma2(wk1.y, h1a[h + 1], t2); t3 = fma2(wk1.y, h1b[h + 1], t3);
        }
        ulonglong2 w3 = *(const ulonglong2*)(W3 + k);
        o0 = fma2(w3.x, relu2(t0), o0);
        o1 = fma2(w3.x, relu2(t1), o1);
        o0 = fma2(w3.y, relu2(t2), o0);
        o1 = fma2(w3.y, relu2(t3), o1);
    }
}

__global__ void __launch_bounds__(256, 4) msg_kernel(const float* __restrict__ adj,
                           const float* __restrict__ adjd,
                           const float* __restrict__ W1,
                           const float* __restrict__ W2,
                           const float* __restrict__ b2,
                           const float* __restrict__ W3,
                           const float* __restrict__ b3) {
    __shared__ __align__(16) ull wa2[2][H], W2d[2][H * H], b2d[2][H], W3d[2][H], b3d[2];
    __shared__ float rcn[2][8][H];
    __shared__ __align__(16) ull ccm2[2][H][64];     // 128 m per block = 64 packs
    int tid = threadIdx.x;
    int mb = blockIdx.x * 128, nb = blockIdx.y * 8;

    if (tid < 16) {
        int s = tid >> 3, h = tid & 7;
        wa2[s][h] = dup2(W1[s * (H * 129) + h * 129]);
        b2d[s][h] = dup2(b2[tid]);
        W3d[s][h] = dup2(W3[tid]);
    }
    if (tid < 2) b3d[tid] = dup2(b3[tid]);
    if (tid >= 32 && tid < 160) {
        int i = tid - 32;
        W2d[i >> 6][i & 63] = dup2(W2[i]);
    }
    if (tid < 128) {
        int s = tid >> 6, r = (tid >> 3) & 7, h = tid & 7;
        rcn[s][r][h] = g_rowpb[s][nb + r][h];
    }
    for (int i = tid; i < 1024; i += 256) {
        int s = i >> 9, h = (i >> 6) & 7, mp = i & 63;
        float2 c = *(const float2*)(&g_colT[s][h][mb + 2 * mp]);
        ccm2[s][h][mp] = pk2(c.x, c.y);
    }
    __syncthreads();

    int mg = tid & 31, nloc = tid >> 5;
    int m0 = mb + 4 * mg, n = nb + nloc;
    float4 av  = *(const float4*)(adj  + n * N + m0);
    float4 adv = *(const float4*)(adjd + n * N + m0);

    {
        ull rc0[H], rc1[H];
#pragma unroll
        for (int h = 0; h < H; h++) {
            ull rn = dup2(rcn[0][nloc][h]);
            ulonglong2 c = *(const ulonglong2*)(&ccm2[0][h][2 * mg]);
            rc0[h] = add2(rn, c.x);
            rc1[h] = add2(rn, c.y);
        }
        ull o0, o1;
        mlp2x2(pk2(av.x, av.y), pk2(av.z, av.w), wa2[0], rc0, rc1,
               W2d[0], b2d[0], W3d[0], b3d[0], o0, o1);
        ulonglong2 v; v.x = o0; v.y = o1;
        *(ulonglong2*)(g_a + n * N + m0) = v;
    }
    {
        ull rc0[H], rc1[H];
#pragma unroll
        for (int h = 0; h < H; h++) {
            ull rn = dup2(rcn[1][nloc][h]);
            ulonglong2 c = *(const ulonglong2*)(&ccm2[1][h][2 * mg]);
            rc0[h] = add2(rn, c.x);
            rc1[h] = add2(rn, c.y);
        }
        ull o0, o1;
        mlp2x2(pk2(adv.x, adv.y), pk2(adv.z, adv.w), wa2[1], rc0, rc1,
               W2d[1], b2d[1], W3d[1], b3d[1], o0, o1);
        ulonglong2 v; v.x = o0; v.y = o1;
        *(ulonglong2*)(g_ad + n * N + m0) = v;
    }
}

// ---------------- xu_first: u_q[layer0] = y @ W[0][q], q=0..4 ----------------
__global__ void __launch_bounds__(256) xu_first_kernel(const float* __restrict__ y,
                                                       const float* __restrict__ gnn_W) {
    extern __shared__ float sm[];
    float* Ws = sm;                  // 5 x [64][PADW]
    float* xs = Ws + 5 * 64 * PADW;  // [8][PADX]
    int tid = threadIdx.x;
    int m0 = blockIdx.x * 8;
    const float* Wbase = gnn_W;      // layer 0

    for (int i = tid; i < 5 * 4096; i += 256) {
        int q = i >> 12, k = (i >> 6) & 63, c = i & 63;
        Ws[q * 64 * PADW + k * PADW + c] = Wbase[i];
    }
    for (int i = tid; i < 8 * D; i += 256) {
        int r = i >> 6, k = i & 63;
        xs[r * PADX + k] = y[(m0 + r) * D + k];
    }
    __syncthreads();

    int r  = tid >> 5;              // 0..7
    int c2 = (tid & 31) * 2;        // 0..62
#pragma unroll
    for (int q = 0; q < 5; q++) {
        const float* Wq = Ws + q * 64 * PADW + c2;
        const float* xr = xs + r * PADX;
        ull acc = 0ull;
#pragma unroll 16
        for (int k = 0; k < 64; k++)
            acc = fma2(dup2(xr[k]), *(const ull*)(Wq + k * PADW), acc);
        *(ull*)(g_u[q] + (m0 + r) * D + c2) = acc;
    }
}

// ---------------- xu: x_l = relu(partials + u4 + b[l]); u_q = x_l @ W[l+1][q] ----------------
__global__ void __launch_bounds__(256) xu_kernel(const float* __restrict__ gnn_W,
                                                 const float* __restrict__ gnn_b,
                                                 int layer) {
    extern __shared__ float sm[];
    float* Ws = sm;                  // 5 x [64][PADW]  (weights of layer+1)
    float* xs = Ws + 5 * 64 * PADW;  // [8][PADX]
    int tid = threadIdx.x;
    int m0 = blockIdx.x * 8;
    const float* Wbase = gnn_W + (layer + 1) * 5 * 4096;

    for (int i = tid; i < 5 * 4096; i += 256) {
        int q = i >> 12, k = (i >> 6) & 63, c = i & 63;
        Ws[q * 64 * PADW + k * PADW + c] = Wbase[i];
    }

    // phase A: reduce partials -> x_l (one f32x2 pair per thread)
    int r  = tid >> 5;              // 0..7
    int c2 = (tid & 31) * 2;        // 0..62
    int off = (m0 + r) * D + c2;
    ull acc = add2(*(const ull*)(g_u[4] + off),
                   pk2(gnn_b[layer * D + c2], gnn_b[layer * D + c2 + 1]));
#pragma unroll
    for (int s = 0; s < NSPLIT; s++)
        acc = add2(acc, *(const ull*)(g_part[s] + off));
    acc = relu2(acc);
    *(ull*)(g_xbuf[layer] + off) = acc;
    *(ull*)(xs + r * PADX + c2) = acc;
    __syncthreads();

    // phase B: u_q for next layer
#pragma unroll
    for (int q = 0; q < 5; q++) {
        const float* Wq = Ws + q * 64 * PADW + c2;
        const float* xr = xs + r * PADX;
        ull a = 0ull;
#pragma unroll 16
        for (int k = 0; k < 64; k++)
            a = fma2(dup2(xr[k]), *(const ull*)(Wq + k * PADW), a);
        *(ull*)(g_u[q] + (m0 + r) * D + c2) = a;
    }
}

// ---------------- fused 4-way product: NT=128, 2 chunks of KC=16, 3 CTA/SM ----------------
__global__ void __launch_bounds__(256, 3) spmm_kernel() {
    extern __shared__ float sm[];
    float* a_ds = sm;                    // [KC][PADA]
    float* a_ts = a_ds + KC * PADA;
    float* d_ds = a_ts + KC * PADA;
    float* d_ts = d_ds + KC * PADA;
    float* u0s  = d_ts + KC * PADA;      // [KC][PADU]
    float* u1s  = u0s + KC * PADU;
    float* u2s  = u1s + KC * PADU;
    float* u3s  = u2s + KC * PADU;

    int tid = threadIdx.x;
    int n0 = blockIdx.x * NT;
    int mbase = blockIdx.y * (NCHUNK * KC);

    int tr = tid >> 4;      // 0..15 -> rows i0 = tr*8
    int tc = tid & 15;      // 0..15 -> cols c0 = tc*4
    int i0 = tr * 8, c0 = tc * 4;

    ull acc[8][2];
#pragma unroll
    for (int i = 0; i < 8; i++) { acc[i][0] = 0ull; acc[i][1] = 0ull; }

#pragma unroll
    for (int chunk = 0; chunk < NCHUNK; chunk++) {
        int m0 = mbase + chunk * KC;
        if (chunk > 0) __syncthreads();    // ensure prior reads done before restage

        // stage direct tiles: read a[(n0+i), m0+j], store [j][i]
        for (int idx = tid; idx < NT * KC; idx += 256) {
            int i = idx >> 4, j = idx & 15;
            a_ds[j * PADA + i] = g_a[(n0 + i) * N + m0 + j];
            d_ds[j * PADA + i] = g_ad[(n0 + i) * N + m0 + j];
        }
        // stage transposed tiles: read a[(m0+j), n0+i] coalesced
        for (int idx = tid; idx < NT * KC; idx += 256) {
            int j = idx >> 7, i = idx & 127;
            a_ts[j * PADA + i] = g_a[(m0 + j) * N + n0 + i];
            d_ts[j * PADA + i] = g_ad[(m0 + j) * N + n0 + i];
        }
        for (int idx = tid; idx < KC * D; idx += 256) {
            int j = idx >> 6, d = idx & 63;
            u0s[j * PADU + d] = g_u[0][(m0 + j) * D + d];
            u1s[j * PADU + d] = g_u[1][(m0 + j) * D + d];
            u2s[j * PADU + d] = g_u[2][(m0 + j) * D + d];
            u3s[j * PADU + d] = g_u[3][(m0 + j) * D + d];
        }
        __syncthreads();

#pragma unroll 2
        for (int j = 0; j < KC; j++) {
            ulonglong2 u0p = *(const ulonglong2*)(u0s + j * PADU + c0);
            ulonglong2 u1p = *(const ulonglong2*)(u1s + j * PADU + c0);
            ulonglong2 u2p = *(const ulonglong2*)(u2s + j * PADU + c0);
            ulonglong2 u3p = *(const ulonglong2*)(u3s + j * PADU + c0);
            float aD[8], aT[8], bD[8], bT[8];
            *(float4*)(aD)     = *(const float4*)(a_ds + j * PADA + i0);
            *(float4*)(aD + 4) = *(const float4*)(a_ds + j * PADA + i0 + 4);
            *(float4*)(aT)     = *(const float4*)(a_ts + j * PADA + i0);
            *(float4*)(aT + 4) = *(const float4*)(a_ts + j * PADA + i0 + 4);
            *(float4*)(bD)     = *(const float4*)(d_ds + j * PADA + i0);
            *(float4*)(bD + 4) = *(const float4*)(d_ds + j * PADA + i0 + 4);
            *(float4*)(bT)     = *(const float4*)(d_ts + j * PADA + i0);
            *(float4*)(bT + 4) = *(const float4*)(d_ts + j * PADA + i0 + 4);
#pragma unroll
            for (int i = 0; i < 8; i++) {
                ull aDd = dup2(aD[i]), aTd = dup2(aT[i]);
                ull bDd = dup2(bD[i]), bTd = dup2(bT[i]);
                acc[i][0] = fma2(aDd, u0p.x, fma2(aTd, u1p.x, fma2(bDd, u2p.x, fma2(bTd, u3p.x, acc[i][0]))));
                acc[i][1] = fma2(aDd, u0p.y, fma2(aTd, u1p.y, fma2(bDd, u2p.y, fma2(bTd, u3p.y, acc[i][1]))));
            }
        }
    }

    float* outp = g_part[blockIdx.y];
#pragma unroll
    for (int i = 0; i < 8; i++) {
        ulonglong2 v; v.x = acc[i][0]; v.y = acc[i][1];
        *(ulonglong2*)(outp + (n0 + i0 + i) * D + c0) = v;
    }
}

// ---------------- final: partials + u4 + b[2], scale by tg ----------------
__global__ void __launch_bounds__(256) final_kernel(float* __restrict__ out,
                                                    const float* __restrict__ gnn_b) {
    int tid = threadIdx.x;
    int m0 = blockIdx.x * 8;            // grid 128
    int r  = tid >> 5;
    int c2 = (tid & 31) * 2;
    int off = (m0 + r) * D + c2;
    ull acc = add2(*(const ull*)(g_u[4] + off),
                   pk2(gnn_b[2 * D + c2], gnn_b[2 * D + c2 + 1]));
#pragma unroll
    for (int s = 0; s < NSPLIT; s++)
        acc = add2(acc, *(const ull*)(g_part[s] + off));
    float tg = 0.f;
#pragma unroll
    for (int s = 0; s < TG_SPLIT; s++) tg += g_tgp[s][m0 + r];
    tg *= (1.0f / N);
    acc = mul2(acc, dup2(tg));
    *(ull*)(out + off) = acc;
}

// ---------------- launch ----------------
extern "C" void kernel_launch(void* const* d_in, const int* in_sizes, int n_in,
                              void* d_out, int out_size) {
    const float* y       = (const float*)d_in[0];
    const float* adj     = (const float*)d_in[1];
    const float* adjd    = (const float*)d_in[2];
    const float* t_grad  = (const float*)d_in[3];
    const float* idx_emb = (const float*)d_in[4];
    const float* msg_W1  = (const float*)d_in[5];
    const float* msg_b1  = (const float*)d_in[6];
    const float* msg_W2  = (const float*)d_in[7];
    const float* msg_b2  = (const float*)d_in[8];
    const float* msg_W3  = (const float*)d_in[9];
    const float* msg_b3  = (const float*)d_in[10];
    const float* gnn_W   = (const float*)d_in[11];
    const float* gnn_b   = (const float*)d_in[12];
    float* out = (float*)d_out;

    const int spmm_smem = (4 * KC * PADA + 4 * KC * PADU) * (int)sizeof(float); // 51,200
    const int xu_smem   = (5 * 64 * PADW + 8 * PADX) * (int)sizeof(float);      // 89,152
    cudaFuncSetAttribute(spmm_kernel, cudaFuncAttributeMaxDynamicSharedMemorySize, spmm_smem);
    cudaFuncSetAttribute(xu_kernel, cudaFuncAttributeMaxDynamicSharedMemorySize, xu_smem);
    cudaFuncSetAttribute(xu_first_kernel, cudaFuncAttributeMaxDynamicSharedMemorySize, xu_smem);

    cudaStream_t s2, s3;
    cudaEvent_t eF, eJ, eU;
    cudaStreamCreateWithFlags(&s2, cudaStreamNonBlocking);
    cudaStreamCreateWithFlags(&s3, cudaStreamNonBlocking);
    cudaEventCreateWithFlags(&eF, cudaEventDisableTiming);
    cudaEventCreateWithFlags(&eJ, cudaEventDisableTiming);
    cudaEventCreateWithFlags(&eU, cudaEventDisableTiming);

    cudaEventRecord(eF, 0);
    cudaStreamWaitEvent(s2, eF, 0);
    cudaStreamWaitEvent(s3, eF, 0);

    // side stream B: tg partials
    tg_kernel<<<dim3(4, TG_SPLIT), 256, 0, s2>>>(t_grad);
    cudaEventRecord(eJ, s2);

    // side stream C: layer-0 u projections (independent of adj path)
    xu_first_kernel<<<128, 256, xu_smem, s3>>>(y, gnn_W);
    cudaEventRecord(eU, s3);

    // main: proj -> msg
    proj_kernel<<<128, 256>>>(idx_emb, msg_W1, msg_b1);
    msg_kernel<<<dim3(8, 128), 256>>>(adj, adjd, msg_W1, msg_W2, msg_b2, msg_W3, msg_b3);

    cudaStreamWaitEvent(0, eU, 0);
    for (int l = 0; l < 3; l++) {
        spmm_kernel<<<dim3(N / NT, NSPLIT), 256, spmm_smem>>>();
        if (l < 2) {
            xu_kernel<<<128, 256, xu_smem>>>(gnn_W, gnn_b, l);
        } else {
            cudaStreamWaitEvent(0, eJ, 0);
            final_kernel<<<128, 256>>>(out, gnn_b);
        }
    }

    // release per-call stream/event resources (side streams already joined)
    cudaEventDestroy(eF);
    cudaEventDestroy(eJ);
    cudaEventDestroy(eU);
    cudaStreamDestroy(s2);
    cudaStreamDestroy(s3);
}